// round 3
// baseline (speedup 1.0000x reference)
#include <cuda_runtime.h>
#include <math_constants.h>
#include <cub/cub.cuh>

#define NROWS 4096
#define HALF_B 2048
#define DDIM 256
#define NT 512
#define IPT 8

// Scratch (static device globals — no allocations anywhere)
__device__ float g_Fn[(size_t)NROWS * DDIM];          // normalized features, 4 MB
__device__ float g_logits[(size_t)NROWS * NROWS];     // logits matrix, 64 MB
__device__ float g_acc;                               // loss accumulator

// RADIX_BITS=6 -> 6 passes over 32-bit keys instead of 8 (default 4 bits).
using BRS = cub::BlockRadixSort<float, NT, IPT, float, 6>;
using BSC = cub::BlockScan<float, NT>;

struct RowSmem {
    float keyL[NROWS];   // pass1: logits row; after sort: sorted keys
    float csum[NROWS];   // inclusive prefix sum of sorted exps
    union {
        typename BRS::TempStorage sort;
        typename BSC::TempStorage scan;
    } cubt;
    float redA[NT / 32];
    float redB[NT / 32];
    float bc[2];
};

// Packed dual-FMA: d = a * b + d, lanewise on 2x f32. Exactly fmaf per lane.
#define FFMA_F32X2(d, a, b) \
    asm("fma.rn.f32x2 %0, %1, %2, %0;" : "+l"(d) : "l"(a), "l"(b))

// ---------------------------------------------------------------------------
// Kernel 1: row-normalize concat([z_i; z_j]) -> g_Fn ; zero the accumulator
// ---------------------------------------------------------------------------
__global__ void k_normalize(const float* __restrict__ zi, const float* __restrict__ zj) {
    int r = blockIdx.x;
    const float* src = (r < HALF_B) ? (zi + (size_t)r * DDIM)
                                    : (zj + (size_t)(r - HALF_B) * DDIM);
    int t = threadIdx.x;  // 64 threads, 4 floats each
    float4 v = reinterpret_cast<const float4*>(src)[t];
    float s = v.x * v.x + v.y * v.y + v.z * v.z + v.w * v.w;
#pragma unroll
    for (int o = 16; o; o >>= 1) s += __shfl_xor_sync(0xffffffffu, s, o);
    __shared__ float ws[2];
    if ((t & 31) == 0) ws[t >> 5] = s;
    __syncthreads();
    float inv = 1.0f / sqrtf(ws[0] + ws[1]);
    float4 o4 = make_float4(v.x * inv, v.y * inv, v.z * inv, v.w * inv);
    reinterpret_cast<float4*>(g_Fn + (size_t)r * DDIM)[t] = o4;
    if (r == 0 && t == 0) g_acc = 0.0f;
}

// ---------------------------------------------------------------------------
// Kernel 2: logits = (Fn @ Fn^T) * 0.5 — symmetric tiled fp32 GEMM with
// packed f32x2 FMAs. 128x128 tile, 256 threads, 8x8 microtile (as 8x4 f32x2),
// BK=16. Triangular 1-D grid; mirror-write the transposed tile.
// ---------------------------------------------------------------------------
__global__ void __launch_bounds__(256) k_gemm() {
    // triangular decode: blockIdx.x -> (by >= bx)
    int b = blockIdx.x;
    int by = (int)((sqrtf(8.0f * b + 1.0f) - 1.0f) * 0.5f);
    while ((by + 1) * (by + 2) / 2 <= b) by++;
    while (by * (by + 1) / 2 > b) by--;
    int bx = b - by * (by + 1) / 2;

    __shared__ float As[16][128];
    __shared__ float Bs[16][128];
    int tid = threadIdx.x;
    int tx = tid & 15, ty = tid >> 4;

    unsigned long long acc2[8][4];  // 8 rows x 4 f32x2 col-pairs
#pragma unroll
    for (int ii = 0; ii < 8; ii++)
#pragma unroll
        for (int jp = 0; jp < 4; jp++) acc2[ii][jp] = 0ULL;

    const float* A0 = g_Fn + (size_t)by * 128 * DDIM;
    const float* B0 = g_Fn + (size_t)bx * 128 * DDIM;

    for (int kt = 0; kt < DDIM; kt += 16) {
#pragma unroll
        for (int q = 0; q < 2; q++) {
            int slot = tid + q * 256;        // 512 float4 slots per tile
            int r = slot >> 2;               // 0..127
            int c4 = (slot & 3) << 2;        // 0,4,8,12
            float4 va = *reinterpret_cast<const float4*>(A0 + (size_t)r * DDIM + kt + c4);
            As[c4 + 0][r] = va.x; As[c4 + 1][r] = va.y;
            As[c4 + 2][r] = va.z; As[c4 + 3][r] = va.w;
            float4 vb = *reinterpret_cast<const float4*>(B0 + (size_t)r * DDIM + kt + c4);
            Bs[c4 + 0][r] = vb.x; Bs[c4 + 1][r] = vb.y;
            Bs[c4 + 2][r] = vb.z; Bs[c4 + 3][r] = vb.w;
        }
        __syncthreads();
#pragma unroll
        for (int kk = 0; kk < 16; kk++) {
            float a[8];
            *reinterpret_cast<float4*>(a)     = *reinterpret_cast<float4*>(&As[kk][ty * 8]);
            *reinterpret_cast<float4*>(a + 4) = *reinterpret_cast<float4*>(&As[kk][ty * 8 + 4]);
            unsigned long long b2[4];
            const unsigned long long* bp =
                reinterpret_cast<const unsigned long long*>(&Bs[kk][tx * 8]);
            b2[0] = bp[0]; b2[1] = bp[1]; b2[2] = bp[2]; b2[3] = bp[3];
#pragma unroll
            for (int ii = 0; ii < 8; ii++) {
                unsigned long long a2;
                asm("mov.b64 %0, {%1, %1};" : "=l"(a2) : "r"(__float_as_uint(a[ii])));
#pragma unroll
                for (int jp = 0; jp < 4; jp++)
                    FFMA_F32X2(acc2[ii][jp], a2, b2[jp]);
            }
        }
        __syncthreads();
    }

    const float sc = 0.5f;  // 1 / TEMPERATURE
    int row0 = by * 128 + ty * 8;
    int col0 = bx * 128 + tx * 8;

    float accf[8][8];
#pragma unroll
    for (int ii = 0; ii < 8; ii++)
#pragma unroll
        for (int jp = 0; jp < 4; jp++) {
            accf[ii][2 * jp + 0] = __uint_as_float((unsigned)(acc2[ii][jp])) * sc;
            accf[ii][2 * jp + 1] = __uint_as_float((unsigned)(acc2[ii][jp] >> 32)) * sc;
        }

#pragma unroll
    for (int ii = 0; ii < 8; ii++) {
        float* dst = g_logits + (size_t)(row0 + ii) * NROWS + col0;
        *reinterpret_cast<float4*>(dst)     = *reinterpret_cast<float4*>(&accf[ii][0]);
        *reinterpret_cast<float4*>(dst + 4) = *reinterpret_cast<float4*>(&accf[ii][4]);
    }
    if (bx < by) {
#pragma unroll
        for (int jj = 0; jj < 8; jj++) {
            float4 w0 = make_float4(accf[0][jj], accf[1][jj], accf[2][jj], accf[3][jj]);
            float4 w1 = make_float4(accf[4][jj], accf[5][jj], accf[6][jj], accf[7][jj]);
            float* dst = g_logits + (size_t)(col0 + jj) * NROWS + row0;
            *reinterpret_cast<float4*>(dst)     = w0;
            *reinterpret_cast<float4*>(dst + 4) = w1;
        }
    }
}

// ---------------------------------------------------------------------------
// Kernel 3: per-row RnC reduction. One block per row.
// ---------------------------------------------------------------------------
__device__ __forceinline__ float4 ld_label(int r, const float* __restrict__ pi,
                                           const float* __restrict__ pj) {
    return (r < HALF_B) ? reinterpret_cast<const float4*>(pi)[r]
                        : reinterpret_cast<const float4*>(pj)[r - HALF_B];
}

__global__ void __launch_bounds__(NT) k_rows(const float* __restrict__ pi,
                                             const float* __restrict__ pj) {
    extern __shared__ char smem_raw[];
    RowSmem& S = *reinterpret_cast<RowSmem*>(smem_raw);
    const int i = blockIdx.x;
    const int t = threadIdx.x;
    const float* Lrow = g_logits + (size_t)i * NROWS;

    // Pass 1: load logits row into SMEM, reduce max and sum (max incl. diagonal)
    float lmax = -CUDART_INF_F, lsum = 0.f;
#pragma unroll
    for (int k = 0; k < IPT; k++) {
        int j = t + k * NT;
        float v = Lrow[j];
        S.keyL[j] = v;
        lmax = fmaxf(lmax, v);
        lsum += v;
    }
#pragma unroll
    for (int o = 16; o; o >>= 1) {
        lmax = fmaxf(lmax, __shfl_xor_sync(0xffffffffu, lmax, o));
        lsum += __shfl_xor_sync(0xffffffffu, lsum, o);
    }
    if ((t & 31) == 0) { S.redA[t >> 5] = lmax; S.redB[t >> 5] = lsum; }
    __syncthreads();
    if (t < 32) {
        float m = (t < NT / 32) ? S.redA[t] : -CUDART_INF_F;
        float s = (t < NT / 32) ? S.redB[t] : 0.f;
#pragma unroll
        for (int o = 8; o; o >>= 1) {
            m = fmaxf(m, __shfl_xor_sync(0xffffffffu, m, o));
            s += __shfl_xor_sync(0xffffffffu, s, o);
        }
        if (t == 0) { S.bc[0] = m; S.bc[1] = s; }
    }
    __syncthreads();
    const float mx = S.bc[0];
    const float sumL = S.bc[1];
    const float Lii = S.keyL[i];

    // Build (label_diff, exp) pairs, blocked arrangement. Diagonal -> +INF/0 pad.
    float4 li = ld_label(i, pi, pj);
    float keys[IPT], vals[IPT];
#pragma unroll
    for (int k = 0; k < IPT; k++) {
        int j = t * IPT + k;
        if (j == i) {
            keys[k] = CUDART_INF_F;
            vals[k] = 0.f;
        } else {
            float4 lj = ld_label(j, pi, pj);
            keys[k] = fabsf(li.x - lj.x) + fabsf(li.y - lj.y) +
                      fabsf(li.z - lj.z) + fabsf(li.w - lj.w);
            vals[k] = __expf(S.keyL[j] - mx);
        }
    }
    __syncthreads();  // all keyL reads done before sort scratch / key overwrite

    BRS(S.cubt.sort).Sort(keys, vals);  // ascending by key, blocked
    __syncthreads();

    // Inclusive scan of sorted exps -> S.csum ; sorted keys -> S.keyL
    float cloc[IPT];
    float run = 0.f;
#pragma unroll
    for (int k = 0; k < IPT; k++) { run += vals[k]; cloc[k] = run; }
    float prefix;
    BSC(S.cubt.scan).ExclusiveSum(run, prefix);
    __syncthreads();
#pragma unroll
    for (int k = 0; k < IPT; k++) {
        int s = t * IPT + k;
        S.csum[s] = prefix + cloc[k];
        S.keyL[s] = keys[k];
    }
    __syncthreads();
    const float total = S.csum[NROWS - 1];  // pad contributes 0

    // Per sorted element: lower_bound -> below -> log(denom+eps)
    float acc = 0.f;
#pragma unroll
    for (int k = 0; k < IPT; k++) {
        int s = t * IPT + k;
        if (s == NROWS - 1) continue;  // the +INF pad sorts last
        float q = keys[k];
        int lo = 0, hi = NROWS;
        while (lo < hi) {
            int mid = (lo + hi) >> 1;
            if (S.keyL[mid] < q) lo = mid + 1; else hi = mid;
        }
        float below = (lo > 0) ? S.csum[lo - 1] : 0.f;
        acc += __logf(total - below + 1e-8f);
    }
#pragma unroll
    for (int o = 16; o; o >>= 1) acc += __shfl_xor_sync(0xffffffffu, acc, o);
    if ((t & 31) == 0) S.redB[t >> 5] = acc;
    __syncthreads();
    if (t < 32) {
        float s = (t < NT / 32) ? S.redB[t] : 0.f;
#pragma unroll
        for (int o = 8; o; o >>= 1) s += __shfl_xor_sync(0xffffffffu, s, o);
        if (t == 0) {
            float sum_logits_o = (sumL - Lii) - (float)(NROWS - 1) * mx;
            atomicAdd(&g_acc, sum_logits_o - s);
        }
    }
}

// ---------------------------------------------------------------------------
// Kernel 4: finalize
// ---------------------------------------------------------------------------
__global__ void k_finalize(float* __restrict__ out) {
    out[0] = -g_acc / 16773120.0f;  // n*(n-1) = 4096*4095
}

// ---------------------------------------------------------------------------
extern "C" void kernel_launch(void* const* d_in, const int* in_sizes, int n_in,
                              void* d_out, int out_size) {
    const float* zi = (const float*)d_in[0];
    const float* zj = (const float*)d_in[1];
    const float* pi = (const float*)d_in[2];
    const float* pj = (const float*)d_in[3];
    float* out = (float*)d_out;

    static bool attr_set = false;
    if (!attr_set) {
        cudaFuncSetAttribute((const void*)k_rows,
                             cudaFuncAttributeMaxDynamicSharedMemorySize,
                             (int)sizeof(RowSmem));
        attr_set = true;
    }

    k_normalize<<<NROWS, 64>>>(zi, zj);

    k_gemm<<<32 * 33 / 2, 256>>>();

    k_rows<<<NROWS, NT, sizeof(RowSmem)>>>(pi, pj);

    k_finalize<<<1, 1>>>(out);
}

// round 6
// speedup vs baseline: 2.1306x; 2.1306x over previous
#include <cuda_runtime.h>
#include <math_constants.h>

#define NROWS 4096
#define HALF_B 2048
#define DDIM 256
#define NT 512
#define IPT 8
#define NBUK 2048
#define BPT (NBUK / NT)   // buckets per thread in scans = 4
#define NWARP (NT / 32)

// Scratch (static device globals — no allocations anywhere)
__device__ float g_Fn[(size_t)NROWS * DDIM];          // normalized features, 4 MB
__device__ float g_logits[(size_t)NROWS * NROWS];     // logits matrix, 64 MB
__device__ float g_acc;                               // loss accumulator

struct RowSmem {
    float keyS[NROWS];     // phase 1: logits row ; phase 2: bucket-scattered keys
    float expS[NROWS];     // bucket-scattered exps
    float histF[NBUK];     // per-bucket exp sums -> exclusive prefix P[b]
    int   offs[NBUK + 1];  // exclusive scan of counts
    int   cnt[NBUK];       // counts, then scatter cursors
    float redA[NWARP];
    float redB[NWARP];
    float fwarp[NWARP];
    int   iwarp[NWARP];
    float bc[4];
};

// ---------------------------------------------------------------------------
// warp scan helpers
// ---------------------------------------------------------------------------
__device__ __forceinline__ int warp_incscan_i(int x, int lane) {
#pragma unroll
    for (int o = 1; o < 32; o <<= 1) {
        int y = __shfl_up_sync(0xffffffffu, x, o);
        if (lane >= o) x += y;
    }
    return x;
}
__device__ __forceinline__ float warp_incscan_f(float x, int lane) {
#pragma unroll
    for (int o = 1; o < 32; o <<= 1) {
        float y = __shfl_up_sync(0xffffffffu, x, o);
        if (lane >= o) x += y;
    }
    return x;
}

// ---------------------------------------------------------------------------
// Kernel 1: row-normalize concat([z_i; z_j]) -> g_Fn ; zero the accumulator
// ---------------------------------------------------------------------------
__global__ void k_normalize(const float* __restrict__ zi, const float* __restrict__ zj) {
    int r = blockIdx.x;
    const float* src = (r < HALF_B) ? (zi + (size_t)r * DDIM)
                                    : (zj + (size_t)(r - HALF_B) * DDIM);
    int t = threadIdx.x;  // 64 threads, 4 floats each
    float4 v = reinterpret_cast<const float4*>(src)[t];
    float s = v.x * v.x + v.y * v.y + v.z * v.z + v.w * v.w;
#pragma unroll
    for (int o = 16; o; o >>= 1) s += __shfl_xor_sync(0xffffffffu, s, o);
    __shared__ float ws[2];
    if ((t & 31) == 0) ws[t >> 5] = s;
    __syncthreads();
    float inv = 1.0f / sqrtf(ws[0] + ws[1]);
    float4 o4 = make_float4(v.x * inv, v.y * inv, v.z * inv, v.w * inv);
    reinterpret_cast<float4*>(g_Fn + (size_t)r * DDIM)[t] = o4;
    if (r == 0 && t == 0) g_acc = 0.0f;
}

// ---------------------------------------------------------------------------
// Kernel 2: logits = (Fn @ Fn^T) * 0.5 — symmetric tiled fp32 GEMM
// ---------------------------------------------------------------------------
__global__ void __launch_bounds__(256) k_gemm() {
    int b = blockIdx.x;
    int by = (int)((sqrtf(8.0f * b + 1.0f) - 1.0f) * 0.5f);
    while ((by + 1) * (by + 2) / 2 <= b) by++;
    while (by * (by + 1) / 2 > b) by--;
    int bx = b - by * (by + 1) / 2;

    __shared__ float As[16][128];
    __shared__ float Bs[16][128];
    int tid = threadIdx.x;
    int tx = tid & 15, ty = tid >> 4;
    float acc[8][8];
#pragma unroll
    for (int ii = 0; ii < 8; ii++)
#pragma unroll
        for (int jj = 0; jj < 8; jj++) acc[ii][jj] = 0.f;

    const float* A0 = g_Fn + (size_t)by * 128 * DDIM;
    const float* B0 = g_Fn + (size_t)bx * 128 * DDIM;

    for (int kt = 0; kt < DDIM; kt += 16) {
#pragma unroll
        for (int q = 0; q < 2; q++) {
            int slot = tid + q * 256;
            int r = slot >> 2;
            int c4 = (slot & 3) << 2;
            float4 va = *reinterpret_cast<const float4*>(A0 + (size_t)r * DDIM + kt + c4);
            As[c4 + 0][r] = va.x; As[c4 + 1][r] = va.y;
            As[c4 + 2][r] = va.z; As[c4 + 3][r] = va.w;
            float4 vb = *reinterpret_cast<const float4*>(B0 + (size_t)r * DDIM + kt + c4);
            Bs[c4 + 0][r] = vb.x; Bs[c4 + 1][r] = vb.y;
            Bs[c4 + 2][r] = vb.z; Bs[c4 + 3][r] = vb.w;
        }
        __syncthreads();
#pragma unroll
        for (int kk = 0; kk < 16; kk++) {
            float a[8], bb[8];
            *reinterpret_cast<float4*>(a)      = *reinterpret_cast<float4*>(&As[kk][ty * 8]);
            *reinterpret_cast<float4*>(a + 4)  = *reinterpret_cast<float4*>(&As[kk][ty * 8 + 4]);
            *reinterpret_cast<float4*>(bb)     = *reinterpret_cast<float4*>(&Bs[kk][tx * 8]);
            *reinterpret_cast<float4*>(bb + 4) = *reinterpret_cast<float4*>(&Bs[kk][tx * 8 + 4]);
#pragma unroll
            for (int ii = 0; ii < 8; ii++)
#pragma unroll
                for (int jj = 0; jj < 8; jj++)
                    acc[ii][jj] = fmaf(a[ii], bb[jj], acc[ii][jj]);
        }
        __syncthreads();
    }

    const float sc = 0.5f;  // 1 / TEMPERATURE
    int row0 = by * 128 + ty * 8;
    int col0 = bx * 128 + tx * 8;
#pragma unroll
    for (int ii = 0; ii < 8; ii++) {
        float4 w0 = make_float4(acc[ii][0] * sc, acc[ii][1] * sc, acc[ii][2] * sc, acc[ii][3] * sc);
        float4 w1 = make_float4(acc[ii][4] * sc, acc[ii][5] * sc, acc[ii][6] * sc, acc[ii][7] * sc);
        float* dst = g_logits + (size_t)(row0 + ii) * NROWS + col0;
        *reinterpret_cast<float4*>(dst)     = w0;
        *reinterpret_cast<float4*>(dst + 4) = w1;
    }
    if (bx < by) {
#pragma unroll
        for (int jj = 0; jj < 8; jj++) {
            float4 w0 = make_float4(acc[0][jj] * sc, acc[1][jj] * sc, acc[2][jj] * sc, acc[3][jj] * sc);
            float4 w1 = make_float4(acc[4][jj] * sc, acc[5][jj] * sc, acc[6][jj] * sc, acc[7][jj] * sc);
            float* dst = g_logits + (size_t)(col0 + jj) * NROWS + row0;
            *reinterpret_cast<float4*>(dst)     = w0;
            *reinterpret_cast<float4*>(dst + 4) = w1;
        }
    }
}

// ---------------------------------------------------------------------------
// Kernel 3: per-row RnC reduction, sort-free bucketed counting scheme.
// below_j = P[bucket_j] + sum of exps in bucket_j with key strictly < key_j.
// ---------------------------------------------------------------------------
__device__ __forceinline__ float4 ld_label(int r, const float* __restrict__ pi,
                                           const float* __restrict__ pj) {
    return (r < HALF_B) ? reinterpret_cast<const float4*>(pi)[r]
                        : reinterpret_cast<const float4*>(pj)[r - HALF_B];
}

__global__ void __launch_bounds__(NT) k_rows(const float* __restrict__ pi,
                                             const float* __restrict__ pj) {
    extern __shared__ char smem_raw[];
    RowSmem& S = *reinterpret_cast<RowSmem*>(smem_raw);
    const int i = blockIdx.x;
    const int t = threadIdx.x;
    const int lane = t & 31, wid = t >> 5;
    const float* Lrow = g_logits + (size_t)i * NROWS;

    // --- Pass 1: stage logits row in SMEM; reduce row max & sum -------------
    float lmax = -CUDART_INF_F, lsum = 0.f;
#pragma unroll
    for (int k = 0; k < IPT; k++) {
        int j = t + k * NT;
        float v = Lrow[j];
        S.keyS[j] = v;
        lmax = fmaxf(lmax, v);
        lsum += v;
    }
#pragma unroll
    for (int o = 16; o; o >>= 1) {
        lmax = fmaxf(lmax, __shfl_xor_sync(0xffffffffu, lmax, o));
        lsum += __shfl_xor_sync(0xffffffffu, lsum, o);
    }
    if (lane == 0) { S.redA[wid] = lmax; S.redB[wid] = lsum; }
    __syncthreads();
    if (t < 32) {
        float m = (t < NWARP) ? S.redA[t] : -CUDART_INF_F;
        float s = (t < NWARP) ? S.redB[t] : 0.f;
#pragma unroll
        for (int o = 8; o; o >>= 1) {
            m = fmaxf(m, __shfl_xor_sync(0xffffffffu, m, o));
            s += __shfl_xor_sync(0xffffffffu, s, o);
        }
        if (t == 0) { S.bc[0] = m; S.bc[1] = s; }
    }
    __syncthreads();
    const float mx = S.bc[0];
    const float sumL = S.bc[1];
    const float Lii = S.keyS[i];

    // --- Pass 2: per-item key / exp / bucket (strided j = t + k*NT) ---------
    float4 li = ld_label(i, pi, pj);
    float key[IPT], ex[IPT];
    int bk[IPT];
    float esum = 0.f;
#pragma unroll
    for (int k = 0; k < IPT; k++) {
        int j = t + k * NT;
        if (j == i) {
            bk[k] = -1; key[k] = 0.f; ex[k] = 0.f;
        } else {
            float4 lj = ld_label(j, pi, pj);
            float q = fabsf(li.x - lj.x) + fabsf(li.y - lj.y) +
                      fabsf(li.z - lj.z) + fabsf(li.w - lj.w);
            key[k] = q;
            ex[k] = __expf(S.keyS[j] - mx);
            int b = (int)(q * (float)(NBUK / 4));   // key in [0,4]
            bk[k] = (b > NBUK - 1) ? (NBUK - 1) : b;
            esum += ex[k];
        }
    }
    // reduce total exp sum across block -> S.bc[2]
#pragma unroll
    for (int o = 16; o; o >>= 1) esum += __shfl_xor_sync(0xffffffffu, esum, o);
    if (lane == 0) S.redB[wid] = esum;
    __syncthreads();
    if (t < 32) {
        float s = (t < NWARP) ? S.redB[t] : 0.f;
#pragma unroll
        for (int o = 8; o; o >>= 1) s += __shfl_xor_sync(0xffffffffu, s, o);
        if (t == 0) S.bc[2] = s;
    }

    // zero histograms (each thread owns BPT consecutive buckets)
#pragma unroll
    for (int k = 0; k < BPT; k++) {
        S.histF[t * BPT + k] = 0.f;
        S.cnt[t * BPT + k] = 0;
    }
    __syncthreads();

    // --- count phase ---------------------------------------------------------
#pragma unroll
    for (int k = 0; k < IPT; k++) {
        if (bk[k] >= 0) {
            atomicAdd(&S.cnt[bk[k]], 1);
            atomicAdd(&S.histF[bk[k]], ex[k]);
        }
    }
    __syncthreads();
    const float total = S.bc[2];

    // --- exclusive scans over NBUK buckets ----------------------------------
    int iloc[BPT]; int irun = 0;
#pragma unroll
    for (int k = 0; k < BPT; k++) { iloc[k] = irun; irun += S.cnt[t * BPT + k]; }
    float floc[BPT]; float frun = 0.f;
#pragma unroll
    for (int k = 0; k < BPT; k++) { floc[k] = frun; frun += S.histF[t * BPT + k]; }

    int iinc = warp_incscan_i(irun, lane);
    float finc = warp_incscan_f(frun, lane);
    if (lane == 31) { S.iwarp[wid] = iinc; S.fwarp[wid] = finc; }
    __syncthreads();
    if (t < 32) {
        int v = (t < NWARP) ? S.iwarp[t] : 0;
        float f = (t < NWARP) ? S.fwarp[t] : 0.f;
        int vi = warp_incscan_i(v, t);
        float fi = warp_incscan_f(f, t);
        if (t < NWARP) { S.iwarp[t] = vi - v; S.fwarp[t] = fi - f; }
    }
    __syncthreads();
    int ibase = S.iwarp[wid] + (iinc - irun);
    float fbase = S.fwarp[wid] + (finc - frun);
#pragma unroll
    for (int k = 0; k < BPT; k++) {
        S.offs[t * BPT + k] = ibase + iloc[k];
        S.histF[t * BPT + k] = fbase + floc[k];   // P[b], exclusive
    }
    if (t == 0) S.offs[NBUK] = NROWS - 1;
    __syncthreads();

    // cursors = offs
#pragma unroll
    for (int k = 0; k < BPT; k++) S.cnt[t * BPT + k] = S.offs[t * BPT + k];
    __syncthreads();

    // --- scatter (keyS safe to overwrite: all reads happened in pass 2) -----
#pragma unroll
    for (int k = 0; k < IPT; k++) {
        if (bk[k] >= 0) {
            int p = atomicAdd(&S.cnt[bk[k]], 1);
            S.keyS[p] = key[k];
            S.expS[p] = ex[k];
        }
    }
    __syncthreads();

    // --- pass B: below = P[b] + strictly-smaller-in-bucket; accumulate log --
    float acc = 0.f;
#pragma unroll
    for (int k = 0; k < IPT; k++) {
        if (bk[k] < 0) continue;
        int b = bk[k];
        float q = key[k];
        float below = S.histF[b];
        int lo = S.offs[b], hi = S.offs[b + 1];
        for (int idx = lo; idx < hi; ++idx) {
            float kk = S.keyS[idx];
            if (kk < q) below += S.expS[idx];
        }
        acc += __logf(total - below + 1e-8f);
    }
#pragma unroll
    for (int o = 16; o; o >>= 1) acc += __shfl_xor_sync(0xffffffffu, acc, o);
    if (lane == 0) S.redB[wid] = acc;
    __syncthreads();
    if (t < 32) {
        float s = (t < NWARP) ? S.redB[t] : 0.f;
#pragma unroll
        for (int o = 8; o; o >>= 1) s += __shfl_xor_sync(0xffffffffu, s, o);
        if (t == 0) {
            float sum_logits_o = (sumL - Lii) - (float)(NROWS - 1) * mx;
            atomicAdd(&g_acc, sum_logits_o - s);
        }
    }
}

// ---------------------------------------------------------------------------
// Kernel 4: finalize
// ---------------------------------------------------------------------------
__global__ void k_finalize(float* __restrict__ out) {
    out[0] = -g_acc / 16773120.0f;  // n*(n-1) = 4096*4095
}

// ---------------------------------------------------------------------------
extern "C" void kernel_launch(void* const* d_in, const int* in_sizes, int n_in,
                              void* d_out, int out_size) {
    const float* zi = (const float*)d_in[0];
    const float* zj = (const float*)d_in[1];
    const float* pi = (const float*)d_in[2];
    const float* pj = (const float*)d_in[3];
    float* out = (float*)d_out;

    static bool attr_set = false;
    if (!attr_set) {
        cudaFuncSetAttribute((const void*)k_rows,
                             cudaFuncAttributeMaxDynamicSharedMemorySize,
                             (int)sizeof(RowSmem));
        attr_set = true;
    }

    k_normalize<<<NROWS, 64>>>(zi, zj);
    k_gemm<<<32 * 33 / 2, 256>>>();
    k_rows<<<NROWS, NT, sizeof(RowSmem)>>>(pi, pj);
    k_finalize<<<1, 1>>>(out);
}

// round 7
// speedup vs baseline: 2.1652x; 1.0162x over previous
#include <cuda_runtime.h>
#include <math_constants.h>

#define NROWS 4096
#define HALF_B 2048
#define DDIM 256
#define NT 512
#define IPT 8
#define NBUK 2048
#define BPT (NBUK / NT)   // buckets per thread in scans = 4
#define NWARP (NT / 32)

// Scratch (static device globals — no allocations anywhere)
__device__ float g_Fn[(size_t)NROWS * DDIM];          // normalized features, 4 MB
__device__ float g_logits[(size_t)NROWS * NROWS];     // logits matrix, 64 MB
__device__ float g_acc;                               // loss accumulator

struct RowSmem {
    float keyS[NROWS];     // phase 1: logits row ; phase 2: bucket-scattered keys
    float expS[NROWS];     // bucket-scattered exps
    float histF[NBUK];     // per-bucket exp sums -> exclusive prefix P[b]
    int   offs[NBUK + 1];  // exclusive scan of counts
    int   cnt[NBUK];       // counts, then scatter cursors
    float redA[NWARP];
    float redB[NWARP];
    float fwarp[NWARP];
    int   iwarp[NWARP];
    float bc[4];
};

// Packed dual-FMA: d = a * b + d, lanewise on 2x f32. Exactly fmaf per lane.
#define FFMA_F32X2(d, a, b) \
    asm("fma.rn.f32x2 %0, %1, %2, %0;" : "+l"(d) : "l"(a), "l"(b))

// ---------------------------------------------------------------------------
// warp scan helpers
// ---------------------------------------------------------------------------
__device__ __forceinline__ int warp_incscan_i(int x, int lane) {
#pragma unroll
    for (int o = 1; o < 32; o <<= 1) {
        int y = __shfl_up_sync(0xffffffffu, x, o);
        if (lane >= o) x += y;
    }
    return x;
}
__device__ __forceinline__ float warp_incscan_f(float x, int lane) {
#pragma unroll
    for (int o = 1; o < 32; o <<= 1) {
        float y = __shfl_up_sync(0xffffffffu, x, o);
        if (lane >= o) x += y;
    }
    return x;
}

// ---------------------------------------------------------------------------
// Kernel 1: row-normalize concat([z_i; z_j]) -> g_Fn ; zero the accumulator
// ---------------------------------------------------------------------------
__global__ void k_normalize(const float* __restrict__ zi, const float* __restrict__ zj) {
    int r = blockIdx.x;
    const float* src = (r < HALF_B) ? (zi + (size_t)r * DDIM)
                                    : (zj + (size_t)(r - HALF_B) * DDIM);
    int t = threadIdx.x;  // 64 threads, 4 floats each
    float4 v = reinterpret_cast<const float4*>(src)[t];
    float s = v.x * v.x + v.y * v.y + v.z * v.z + v.w * v.w;
#pragma unroll
    for (int o = 16; o; o >>= 1) s += __shfl_xor_sync(0xffffffffu, s, o);
    __shared__ float ws[2];
    if ((t & 31) == 0) ws[t >> 5] = s;
    __syncthreads();
    float inv = 1.0f / sqrtf(ws[0] + ws[1]);
    float4 o4 = make_float4(v.x * inv, v.y * inv, v.z * inv, v.w * inv);
    reinterpret_cast<float4*>(g_Fn + (size_t)r * DDIM)[t] = o4;
    if (r == 0 && t == 0) g_acc = 0.0f;
}

// ---------------------------------------------------------------------------
// Kernel 2: logits = (Fn @ Fn^T) * 0.5 — symmetric tiled fp32 GEMM with
// packed f32x2 FMAs (FFMA2). Same tiling as R6; only the inner product and
// accumulator layout changed. Per-lane arithmetic identical to fmaf.
// ---------------------------------------------------------------------------
__global__ void __launch_bounds__(256) k_gemm() {
    int b = blockIdx.x;
    int by = (int)((sqrtf(8.0f * b + 1.0f) - 1.0f) * 0.5f);
    while ((by + 1) * (by + 2) / 2 <= b) by++;
    while (by * (by + 1) / 2 > b) by--;
    int bx = b - by * (by + 1) / 2;

    __shared__ float As[16][128];
    __shared__ float Bs[16][128];
    int tid = threadIdx.x;
    int tx = tid & 15, ty = tid >> 4;

    unsigned long long acc2[8][4];  // 8 rows x 4 f32x2 col-pairs
#pragma unroll
    for (int ii = 0; ii < 8; ii++)
#pragma unroll
        for (int jp = 0; jp < 4; jp++) acc2[ii][jp] = 0ULL;

    const float* A0 = g_Fn + (size_t)by * 128 * DDIM;
    const float* B0 = g_Fn + (size_t)bx * 128 * DDIM;

    for (int kt = 0; kt < DDIM; kt += 16) {
#pragma unroll
        for (int q = 0; q < 2; q++) {
            int slot = tid + q * 256;
            int r = slot >> 2;
            int c4 = (slot & 3) << 2;
            float4 va = *reinterpret_cast<const float4*>(A0 + (size_t)r * DDIM + kt + c4);
            As[c4 + 0][r] = va.x; As[c4 + 1][r] = va.y;
            As[c4 + 2][r] = va.z; As[c4 + 3][r] = va.w;
            float4 vb = *reinterpret_cast<const float4*>(B0 + (size_t)r * DDIM + kt + c4);
            Bs[c4 + 0][r] = vb.x; Bs[c4 + 1][r] = vb.y;
            Bs[c4 + 2][r] = vb.z; Bs[c4 + 3][r] = vb.w;
        }
        __syncthreads();
#pragma unroll
        for (int kk = 0; kk < 16; kk++) {
            float a[8];
            *reinterpret_cast<float4*>(a)     = *reinterpret_cast<float4*>(&As[kk][ty * 8]);
            *reinterpret_cast<float4*>(a + 4) = *reinterpret_cast<float4*>(&As[kk][ty * 8 + 4]);
            unsigned long long b2[4];
            const unsigned long long* bp =
                reinterpret_cast<const unsigned long long*>(&Bs[kk][tx * 8]);
            b2[0] = bp[0]; b2[1] = bp[1]; b2[2] = bp[2]; b2[3] = bp[3];
#pragma unroll
            for (int ii = 0; ii < 8; ii++) {
                unsigned long long a2;
                asm("mov.b64 %0, {%1, %1};" : "=l"(a2) : "r"(__float_as_uint(a[ii])));
#pragma unroll
                for (int jp = 0; jp < 4; jp++)
                    FFMA_F32X2(acc2[ii][jp], a2, b2[jp]);
            }
        }
        __syncthreads();
    }

    const float sc = 0.5f;  // 1 / TEMPERATURE
    int row0 = by * 128 + ty * 8;
    int col0 = bx * 128 + tx * 8;

    float accf[8][8];
#pragma unroll
    for (int ii = 0; ii < 8; ii++)
#pragma unroll
        for (int jp = 0; jp < 4; jp++) {
            accf[ii][2 * jp + 0] = __uint_as_float((unsigned)(acc2[ii][jp])) * sc;
            accf[ii][2 * jp + 1] = __uint_as_float((unsigned)(acc2[ii][jp] >> 32)) * sc;
        }

#pragma unroll
    for (int ii = 0; ii < 8; ii++) {
        float* dst = g_logits + (size_t)(row0 + ii) * NROWS + col0;
        *reinterpret_cast<float4*>(dst)     = *reinterpret_cast<float4*>(&accf[ii][0]);
        *reinterpret_cast<float4*>(dst + 4) = *reinterpret_cast<float4*>(&accf[ii][4]);
    }
    if (bx < by) {
#pragma unroll
        for (int jj = 0; jj < 8; jj++) {
            float4 w0 = make_float4(accf[0][jj], accf[1][jj], accf[2][jj], accf[3][jj]);
            float4 w1 = make_float4(accf[4][jj], accf[5][jj], accf[6][jj], accf[7][jj]);
            float* dst = g_logits + (size_t)(col0 + jj) * NROWS + row0;
            *reinterpret_cast<float4*>(dst)     = w0;
            *reinterpret_cast<float4*>(dst + 4) = w1;
        }
    }
}

// ---------------------------------------------------------------------------
// Kernel 3: per-row RnC reduction, sort-free bucketed counting (R6 exact).
// ---------------------------------------------------------------------------
__device__ __forceinline__ float4 ld_label(int r, const float* __restrict__ pi,
                                           const float* __restrict__ pj) {
    return (r < HALF_B) ? reinterpret_cast<const float4*>(pi)[r]
                        : reinterpret_cast<const float4*>(pj)[r - HALF_B];
}

__global__ void __launch_bounds__(NT) k_rows(const float* __restrict__ pi,
                                             const float* __restrict__ pj) {
    extern __shared__ char smem_raw[];
    RowSmem& S = *reinterpret_cast<RowSmem*>(smem_raw);
    const int i = blockIdx.x;
    const int t = threadIdx.x;
    const int lane = t & 31, wid = t >> 5;
    const float* Lrow = g_logits + (size_t)i * NROWS;

    // --- Pass 1: stage logits row in SMEM; reduce row max & sum -------------
    float lmax = -CUDART_INF_F, lsum = 0.f;
#pragma unroll
    for (int k = 0; k < IPT; k++) {
        int j = t + k * NT;
        float v = Lrow[j];
        S.keyS[j] = v;
        lmax = fmaxf(lmax, v);
        lsum += v;
    }
#pragma unroll
    for (int o = 16; o; o >>= 1) {
        lmax = fmaxf(lmax, __shfl_xor_sync(0xffffffffu, lmax, o));
        lsum += __shfl_xor_sync(0xffffffffu, lsum, o);
    }
    if (lane == 0) { S.redA[wid] = lmax; S.redB[wid] = lsum; }
    __syncthreads();
    if (t < 32) {
        float m = (t < NWARP) ? S.redA[t] : -CUDART_INF_F;
        float s = (t < NWARP) ? S.redB[t] : 0.f;
#pragma unroll
        for (int o = 8; o; o >>= 1) {
            m = fmaxf(m, __shfl_xor_sync(0xffffffffu, m, o));
            s += __shfl_xor_sync(0xffffffffu, s, o);
        }
        if (t == 0) { S.bc[0] = m; S.bc[1] = s; }
    }
    __syncthreads();
    const float mx = S.bc[0];
    const float sumL = S.bc[1];
    const float Lii = S.keyS[i];

    // --- Pass 2: per-item key / exp / bucket (strided j = t + k*NT) ---------
    float4 li = ld_label(i, pi, pj);
    float key[IPT], ex[IPT];
    int bk[IPT];
    float esum = 0.f;
#pragma unroll
    for (int k = 0; k < IPT; k++) {
        int j = t + k * NT;
        if (j == i) {
            bk[k] = -1; key[k] = 0.f; ex[k] = 0.f;
        } else {
            float4 lj = ld_label(j, pi, pj);
            float q = fabsf(li.x - lj.x) + fabsf(li.y - lj.y) +
                      fabsf(li.z - lj.z) + fabsf(li.w - lj.w);
            key[k] = q;
            ex[k] = __expf(S.keyS[j] - mx);
            int b = (int)(q * (float)(NBUK / 4));   // key in [0,4]
            bk[k] = (b > NBUK - 1) ? (NBUK - 1) : b;
            esum += ex[k];
        }
    }
    // reduce total exp sum across block -> S.bc[2]
#pragma unroll
    for (int o = 16; o; o >>= 1) esum += __shfl_xor_sync(0xffffffffu, esum, o);
    if (lane == 0) S.redB[wid] = esum;
    __syncthreads();
    if (t < 32) {
        float s = (t < NWARP) ? S.redB[t] : 0.f;
#pragma unroll
        for (int o = 8; o; o >>= 1) s += __shfl_xor_sync(0xffffffffu, s, o);
        if (t == 0) S.bc[2] = s;
    }

    // zero histograms (each thread owns BPT consecutive buckets)
#pragma unroll
    for (int k = 0; k < BPT; k++) {
        S.histF[t * BPT + k] = 0.f;
        S.cnt[t * BPT + k] = 0;
    }
    __syncthreads();

    // --- count phase ---------------------------------------------------------
#pragma unroll
    for (int k = 0; k < IPT; k++) {
        if (bk[k] >= 0) {
            atomicAdd(&S.cnt[bk[k]], 1);
            atomicAdd(&S.histF[bk[k]], ex[k]);
        }
    }
    __syncthreads();
    const float total = S.bc[2];

    // --- exclusive scans over NBUK buckets ----------------------------------
    int iloc[BPT]; int irun = 0;
#pragma unroll
    for (int k = 0; k < BPT; k++) { iloc[k] = irun; irun += S.cnt[t * BPT + k]; }
    float floc[BPT]; float frun = 0.f;
#pragma unroll
    for (int k = 0; k < BPT; k++) { floc[k] = frun; frun += S.histF[t * BPT + k]; }

    int iinc = warp_incscan_i(irun, lane);
    float finc = warp_incscan_f(frun, lane);
    if (lane == 31) { S.iwarp[wid] = iinc; S.fwarp[wid] = finc; }
    __syncthreads();
    if (t < 32) {
        int v = (t < NWARP) ? S.iwarp[t] : 0;
        float f = (t < NWARP) ? S.fwarp[t] : 0.f;
        int vi = warp_incscan_i(v, t);
        float fi = warp_incscan_f(f, t);
        if (t < NWARP) { S.iwarp[t] = vi - v; S.fwarp[t] = fi - f; }
    }
    __syncthreads();
    int ibase = S.iwarp[wid] + (iinc - irun);
    float fbase = S.fwarp[wid] + (finc - frun);
#pragma unroll
    for (int k = 0; k < BPT; k++) {
        S.offs[t * BPT + k] = ibase + iloc[k];
        S.histF[t * BPT + k] = fbase + floc[k];   // P[b], exclusive
    }
    if (t == 0) S.offs[NBUK] = NROWS - 1;
    __syncthreads();

    // cursors = offs
#pragma unroll
    for (int k = 0; k < BPT; k++) S.cnt[t * BPT + k] = S.offs[t * BPT + k];
    __syncthreads();

    // --- scatter (keyS safe to overwrite: all reads happened in pass 2) -----
#pragma unroll
    for (int k = 0; k < IPT; k++) {
        if (bk[k] >= 0) {
            int p = atomicAdd(&S.cnt[bk[k]], 1);
            S.keyS[p] = key[k];
            S.expS[p] = ex[k];
        }
    }
    __syncthreads();

    // --- pass B: below = P[b] + strictly-smaller-in-bucket; accumulate log --
    float acc = 0.f;
#pragma unroll
    for (int k = 0; k < IPT; k++) {
        if (bk[k] < 0) continue;
        int b = bk[k];
        float q = key[k];
        float below = S.histF[b];
        int lo = S.offs[b], hi = S.offs[b + 1];
        for (int idx = lo; idx < hi; ++idx) {
            float kk = S.keyS[idx];
            if (kk < q) below += S.expS[idx];
        }
        acc += __logf(total - below + 1e-8f);
    }
#pragma unroll
    for (int o = 16; o; o >>= 1) acc += __shfl_xor_sync(0xffffffffu, acc, o);
    if (lane == 0) S.redB[wid] = acc;
    __syncthreads();
    if (t < 32) {
        float s = (t < NWARP) ? S.redB[t] : 0.f;
#pragma unroll
        for (int o = 8; o; o >>= 1) s += __shfl_xor_sync(0xffffffffu, s, o);
        if (t == 0) {
            float sum_logits_o = (sumL - Lii) - (float)(NROWS - 1) * mx;
            atomicAdd(&g_acc, sum_logits_o - s);
        }
    }
}

// ---------------------------------------------------------------------------
// Kernel 4: finalize
// ---------------------------------------------------------------------------
__global__ void k_finalize(float* __restrict__ out) {
    out[0] = -g_acc / 16773120.0f;  // n*(n-1) = 4096*4095
}

// ---------------------------------------------------------------------------
extern "C" void kernel_launch(void* const* d_in, const int* in_sizes, int n_in,
                              void* d_out, int out_size) {
    const float* zi = (const float*)d_in[0];
    const float* zj = (const float*)d_in[1];
    const float* pi = (const float*)d_in[2];
    const float* pj = (const float*)d_in[3];
    float* out = (float*)d_out;

    static bool attr_set = false;
    if (!attr_set) {
        cudaFuncSetAttribute((const void*)k_rows,
                             cudaFuncAttributeMaxDynamicSharedMemorySize,
                             (int)sizeof(RowSmem));
        attr_set = true;
    }

    k_normalize<<<NROWS, 64>>>(zi, zj);
    k_gemm<<<32 * 33 / 2, 256>>>();
    k_rows<<<NROWS, NT, sizeof(RowSmem)>>>(pi, pj);
    k_finalize<<<1, 1>>>(out);
}

// round 8
// speedup vs baseline: 2.2111x; 1.0212x over previous
#include <cuda_runtime.h>
#include <math_constants.h>

#define NROWS 4096
#define HALF_B 2048
#define DDIM 256
#define NT 512
#define IPT 8
#define NBUK 2048
#define BPT (NBUK / NT)   // buckets per thread in scans = 4
#define NWARP (NT / 32)

// Scratch (static device globals — no allocations anywhere)
__device__ float g_Fn[(size_t)NROWS * DDIM];          // normalized features, 4 MB
__device__ float g_logits[(size_t)NROWS * NROWS];     // logits matrix, 64 MB
__device__ float g_acc;                               // loss accumulator
__device__ unsigned g_done;                           // finished-block counter

struct RowSmem {
    float keyS[NROWS];     // bucket-scattered keys
    float expS[NROWS];     // bucket-scattered exps
    float histF[NBUK];     // per-bucket exp sums -> exclusive prefix P[b]
    int   offs[NBUK + 1];  // exclusive scan of counts
    int   cnt[NBUK];       // counts, then scatter cursors
    float redB[NWARP];
    float fwarp[NWARP];
    int   iwarp[NWARP];
    float bc[4];
};

// Packed dual-FMA: d = a * b + d, lanewise on 2x f32. Exactly fmaf per lane.
#define FFMA_F32X2(d, a, b) \
    asm("fma.rn.f32x2 %0, %1, %2, %0;" : "+l"(d) : "l"(a), "l"(b))

// ---------------------------------------------------------------------------
// warp scan helpers
// ---------------------------------------------------------------------------
__device__ __forceinline__ int warp_incscan_i(int x, int lane) {
#pragma unroll
    for (int o = 1; o < 32; o <<= 1) {
        int y = __shfl_up_sync(0xffffffffu, x, o);
        if (lane >= o) x += y;
    }
    return x;
}
__device__ __forceinline__ float warp_incscan_f(float x, int lane) {
#pragma unroll
    for (int o = 1; o < 32; o <<= 1) {
        float y = __shfl_up_sync(0xffffffffu, x, o);
        if (lane >= o) x += y;
    }
    return x;
}

// ---------------------------------------------------------------------------
// Kernel 1: row-normalize concat([z_i; z_j]) -> g_Fn ; zero accumulators
// ---------------------------------------------------------------------------
__global__ void k_normalize(const float* __restrict__ zi, const float* __restrict__ zj) {
    int r = blockIdx.x;
    const float* src = (r < HALF_B) ? (zi + (size_t)r * DDIM)
                                    : (zj + (size_t)(r - HALF_B) * DDIM);
    int t = threadIdx.x;  // 64 threads, 4 floats each
    float4 v = reinterpret_cast<const float4*>(src)[t];
    float s = v.x * v.x + v.y * v.y + v.z * v.z + v.w * v.w;
#pragma unroll
    for (int o = 16; o; o >>= 1) s += __shfl_xor_sync(0xffffffffu, s, o);
    __shared__ float ws[2];
    if ((t & 31) == 0) ws[t >> 5] = s;
    __syncthreads();
    float inv = 1.0f / sqrtf(ws[0] + ws[1]);
    float4 o4 = make_float4(v.x * inv, v.y * inv, v.z * inv, v.w * inv);
    reinterpret_cast<float4*>(g_Fn + (size_t)r * DDIM)[t] = o4;
    if (r == 0 && t == 0) { g_acc = 0.0f; g_done = 0u; }
}

// ---------------------------------------------------------------------------
// Kernel 2: logits = (Fn @ Fn^T) * 0.5 — symmetric tiled GEMM, f32x2 FMAs
// ---------------------------------------------------------------------------
__global__ void __launch_bounds__(256) k_gemm() {
    int b = blockIdx.x;
    int by = (int)((sqrtf(8.0f * b + 1.0f) - 1.0f) * 0.5f);
    while ((by + 1) * (by + 2) / 2 <= b) by++;
    while (by * (by + 1) / 2 > b) by--;
    int bx = b - by * (by + 1) / 2;

    __shared__ float As[16][128];
    __shared__ float Bs[16][128];
    int tid = threadIdx.x;
    int tx = tid & 15, ty = tid >> 4;

    unsigned long long acc2[8][4];  // 8 rows x 4 f32x2 col-pairs
#pragma unroll
    for (int ii = 0; ii < 8; ii++)
#pragma unroll
        for (int jp = 0; jp < 4; jp++) acc2[ii][jp] = 0ULL;

    const float* A0 = g_Fn + (size_t)by * 128 * DDIM;
    const float* B0 = g_Fn + (size_t)bx * 128 * DDIM;

    for (int kt = 0; kt < DDIM; kt += 16) {
#pragma unroll
        for (int q = 0; q < 2; q++) {
            int slot = tid + q * 256;
            int r = slot >> 2;
            int c4 = (slot & 3) << 2;
            float4 va = *reinterpret_cast<const float4*>(A0 + (size_t)r * DDIM + kt + c4);
            As[c4 + 0][r] = va.x; As[c4 + 1][r] = va.y;
            As[c4 + 2][r] = va.z; As[c4 + 3][r] = va.w;
            float4 vb = *reinterpret_cast<const float4*>(B0 + (size_t)r * DDIM + kt + c4);
            Bs[c4 + 0][r] = vb.x; Bs[c4 + 1][r] = vb.y;
            Bs[c4 + 2][r] = vb.z; Bs[c4 + 3][r] = vb.w;
        }
        __syncthreads();
#pragma unroll
        for (int kk = 0; kk < 16; kk++) {
            float a[8];
            *reinterpret_cast<float4*>(a)     = *reinterpret_cast<float4*>(&As[kk][ty * 8]);
            *reinterpret_cast<float4*>(a + 4) = *reinterpret_cast<float4*>(&As[kk][ty * 8 + 4]);
            unsigned long long b2[4];
            const unsigned long long* bp =
                reinterpret_cast<const unsigned long long*>(&Bs[kk][tx * 8]);
            b2[0] = bp[0]; b2[1] = bp[1]; b2[2] = bp[2]; b2[3] = bp[3];
#pragma unroll
            for (int ii = 0; ii < 8; ii++) {
                unsigned long long a2;
                asm("mov.b64 %0, {%1, %1};" : "=l"(a2) : "r"(__float_as_uint(a[ii])));
#pragma unroll
                for (int jp = 0; jp < 4; jp++)
                    FFMA_F32X2(acc2[ii][jp], a2, b2[jp]);
            }
        }
        __syncthreads();
    }

    const float sc = 0.5f;  // 1 / TEMPERATURE
    int row0 = by * 128 + ty * 8;
    int col0 = bx * 128 + tx * 8;

    float accf[8][8];
#pragma unroll
    for (int ii = 0; ii < 8; ii++)
#pragma unroll
        for (int jp = 0; jp < 4; jp++) {
            accf[ii][2 * jp + 0] = __uint_as_float((unsigned)(acc2[ii][jp])) * sc;
            accf[ii][2 * jp + 1] = __uint_as_float((unsigned)(acc2[ii][jp] >> 32)) * sc;
        }

#pragma unroll
    for (int ii = 0; ii < 8; ii++) {
        float* dst = g_logits + (size_t)(row0 + ii) * NROWS + col0;
        *reinterpret_cast<float4*>(dst)     = *reinterpret_cast<float4*>(&accf[ii][0]);
        *reinterpret_cast<float4*>(dst + 4) = *reinterpret_cast<float4*>(&accf[ii][4]);
    }
    if (bx < by) {
#pragma unroll
        for (int jj = 0; jj < 8; jj++) {
            float4 w0 = make_float4(accf[0][jj], accf[1][jj], accf[2][jj], accf[3][jj]);
            float4 w1 = make_float4(accf[4][jj], accf[5][jj], accf[6][jj], accf[7][jj]);
            float* dst = g_logits + (size_t)(col0 + jj) * NROWS + row0;
            *reinterpret_cast<float4*>(dst)     = w0;
            *reinterpret_cast<float4*>(dst + 4) = w1;
        }
    }
}

// ---------------------------------------------------------------------------
// Kernel 3: per-row RnC reduction, sort-free bucketed counting.
// mx = diagonal logit (row max up to fp noise; loss is mx-shift invariant to
// ~eps*(e^dmx - 1) ~ 1e-15). Single pass over the row: no SMEM staging.
// Last block to finish writes the final loss (finalize folded in).
// ---------------------------------------------------------------------------
__device__ __forceinline__ float4 ld_label(int r, const float* __restrict__ pi,
                                           const float* __restrict__ pj) {
    return (r < HALF_B) ? reinterpret_cast<const float4*>(pi)[r]
                        : reinterpret_cast<const float4*>(pj)[r - HALF_B];
}

__global__ void __launch_bounds__(NT) k_rows(const float* __restrict__ pi,
                                             const float* __restrict__ pj,
                                             float* __restrict__ out) {
    extern __shared__ char smem_raw[];
    RowSmem& S = *reinterpret_cast<RowSmem*>(smem_raw);
    const int i = blockIdx.x;
    const int t = threadIdx.x;
    const int lane = t & 31, wid = t >> 5;
    const float* Lrow = g_logits + (size_t)i * NROWS;

    const float mx = __ldg(Lrow + i);   // diagonal = row max (broadcast load)
    float4 li = ld_label(i, pi, pj);

    // --- Single pass: load logit, key/exp/bucket; accumulate row sum --------
    float key[IPT], ex[IPT];
    int bk[IPT];
    float lsum = 0.f;
#pragma unroll
    for (int k = 0; k < IPT; k++) {
        int j = t + k * NT;
        float v = Lrow[j];
        lsum += v;
        if (j == i) {
            bk[k] = -1; key[k] = 0.f; ex[k] = 0.f;
        } else {
            float4 lj = ld_label(j, pi, pj);
            float q = fabsf(li.x - lj.x) + fabsf(li.y - lj.y) +
                      fabsf(li.z - lj.z) + fabsf(li.w - lj.w);
            key[k] = q;
            ex[k] = __expf(v - mx);
            int b = (int)(q * (float)(NBUK / 4));   // key in [0,4]
            bk[k] = (b > NBUK - 1) ? (NBUK - 1) : b;
        }
    }
    // warp-reduce lsum
#pragma unroll
    for (int o = 16; o; o >>= 1) lsum += __shfl_xor_sync(0xffffffffu, lsum, o);
    if (lane == 0) S.redB[wid] = lsum;

    // zero histograms (each thread owns BPT consecutive buckets)
#pragma unroll
    for (int k = 0; k < BPT; k++) {
        S.histF[t * BPT + k] = 0.f;
        S.cnt[t * BPT + k] = 0;
    }
    __syncthreads();

    // finish lsum reduction -> S.bc[1]
    if (t < 32) {
        float s = (t < NWARP) ? S.redB[t] : 0.f;
#pragma unroll
        for (int o = 8; o; o >>= 1) s += __shfl_xor_sync(0xffffffffu, s, o);
        if (t == 0) S.bc[1] = s;
    }

    // --- count phase ---------------------------------------------------------
#pragma unroll
    for (int k = 0; k < IPT; k++) {
        if (bk[k] >= 0) {
            atomicAdd(&S.cnt[bk[k]], 1);
            atomicAdd(&S.histF[bk[k]], ex[k]);
        }
    }
    __syncthreads();

    // --- exclusive scans over NBUK buckets; grand float total -> S.bc[2] ---
    int iloc[BPT]; int irun = 0;
#pragma unroll
    for (int k = 0; k < BPT; k++) { iloc[k] = irun; irun += S.cnt[t * BPT + k]; }
    float floc[BPT]; float frun = 0.f;
#pragma unroll
    for (int k = 0; k < BPT; k++) { floc[k] = frun; frun += S.histF[t * BPT + k]; }

    int iinc = warp_incscan_i(irun, lane);
    float finc = warp_incscan_f(frun, lane);
    if (lane == 31) { S.iwarp[wid] = iinc; S.fwarp[wid] = finc; }
    __syncthreads();
    if (t < 32) {
        int v = (t < NWARP) ? S.iwarp[t] : 0;
        float f = (t < NWARP) ? S.fwarp[t] : 0.f;
        int vi = warp_incscan_i(v, t);
        float fi = warp_incscan_f(f, t);
        if (t < NWARP) { S.iwarp[t] = vi - v; S.fwarp[t] = fi - f; }
        if (t == NWARP - 1) S.bc[2] = fi;   // grand total of exps
    }
    __syncthreads();
    int ibase = S.iwarp[wid] + (iinc - irun);
    float fbase = S.fwarp[wid] + (finc - frun);
#pragma unroll
    for (int k = 0; k < BPT; k++) {
        S.offs[t * BPT + k] = ibase + iloc[k];
        S.histF[t * BPT + k] = fbase + floc[k];   // P[b], exclusive
    }
    if (t == 0) S.offs[NBUK] = NROWS - 1;
    __syncthreads();

    // cursors = offs
#pragma unroll
    for (int k = 0; k < BPT; k++) S.cnt[t * BPT + k] = S.offs[t * BPT + k];
    __syncthreads();

    const float total = S.bc[2];
    const float sumL = S.bc[1];

    // --- scatter -------------------------------------------------------------
#pragma unroll
    for (int k = 0; k < IPT; k++) {
        if (bk[k] >= 0) {
            int p = atomicAdd(&S.cnt[bk[k]], 1);
            S.keyS[p] = key[k];
            S.expS[p] = ex[k];
        }
    }
    __syncthreads();

    // --- pass B: below = P[b] + strictly-smaller-in-bucket; accumulate log --
    float acc = 0.f;
#pragma unroll
    for (int k = 0; k < IPT; k++) {
        if (bk[k] < 0) continue;
        int b = bk[k];
        float q = key[k];
        float below = S.histF[b];
        int lo = S.offs[b], hi = S.offs[b + 1];
        for (int idx = lo; idx < hi; ++idx) {
            float kk = S.keyS[idx];
            if (kk < q) below += S.expS[idx];
        }
        acc += __logf(total - below + 1e-8f);
    }
#pragma unroll
    for (int o = 16; o; o >>= 1) acc += __shfl_xor_sync(0xffffffffu, acc, o);
    if (lane == 0) S.redB[wid] = acc;
    __syncthreads();
    if (t < 32) {
        float s = (t < NWARP) ? S.redB[t] : 0.f;
#pragma unroll
        for (int o = 8; o; o >>= 1) s += __shfl_xor_sync(0xffffffffu, s, o);
        if (t == 0) {
            float sum_logits_o = (sumL - mx) - (float)(NROWS - 1) * mx;
            atomicAdd(&g_acc, sum_logits_o - s);
            __threadfence();
            unsigned old = atomicAdd(&g_done, 1u);
            if (old == NROWS - 1) {
                float a = atomicAdd(&g_acc, 0.0f);  // coherent read of final sum
                out[0] = -a / 16773120.0f;          // n*(n-1) = 4096*4095
            }
        }
    }
}

// ---------------------------------------------------------------------------
extern "C" void kernel_launch(void* const* d_in, const int* in_sizes, int n_in,
                              void* d_out, int out_size) {
    const float* zi = (const float*)d_in[0];
    const float* zj = (const float*)d_in[1];
    const float* pi = (const float*)d_in[2];
    const float* pj = (const float*)d_in[3];
    float* out = (float*)d_out;

    static bool attr_set = false;
    if (!attr_set) {
        cudaFuncSetAttribute((const void*)k_rows,
                             cudaFuncAttributeMaxDynamicSharedMemorySize,
                             (int)sizeof(RowSmem));
        attr_set = true;
    }

    k_normalize<<<NROWS, 64>>>(zi, zj);
    k_gemm<<<32 * 33 / 2, 256>>>();
    k_rows<<<NROWS, NT, sizeof(RowSmem)>>>(pi, pj, out);
}